// round 3
// baseline (speedup 1.0000x reference)
#include <cuda_runtime.h>
#include <cstdint>
#include <cstddef>

#define N_NODES 100000
#define N_EDGES 120000
#define N_GRAPH 256
#define IN_DIM  162
#define HID     128
#define R_REL   5

// ---------------- scratch (static __device__, no allocation) ----------------
__device__ float g_bufA[(size_t)N_NODES * HID];
__device__ float g_bufB[(size_t)N_NODES * HID];
__device__ float g_M[(size_t)R_REL * N_NODES * HID];   // per-relation messages
__device__ int   g_cnt[R_REL * N_NODES];
__device__ float g_invc[R_REL * N_NODES];
__device__ float g_read[N_GRAPH * HID];

// ---------------- small helpers ----------------
__global__ void zero_cnt_kernel() {
    int i = blockIdx.x * blockDim.x + threadIdx.x;
    if (i < R_REL * N_NODES) g_cnt[i] = 0;
}

__global__ void count_kernel(const int* __restrict__ e1, const int* __restrict__ e2,
                             const int* __restrict__ e3, const int* __restrict__ e4,
                             const int* __restrict__ e5) {
    int r = blockIdx.y;
    const int* eis[R_REL] = {e1, e2, e3, e4, e5};
    const int* ei = eis[r];
    int e = blockIdx.x * blockDim.x + threadIdx.x;
    if (e < N_EDGES) {
        int dst = ei[N_EDGES + e];
        atomicAdd(&g_cnt[r * N_NODES + dst], 1);
    }
}

__global__ void invc_kernel() {
    int i = blockIdx.x * blockDim.x + threadIdx.x;
    if (i < R_REL * N_NODES) {
        int c = g_cnt[i];
        g_invc[i] = 1.0f / (float)(c > 0 ? c : 1);
    }
}

// ---------------- fused layer GEMM ----------------
// C_block(c=0)   : outSelf[n][j] = bias[j] + sum_f A[n][f] * Broot[f][j]
// C_block(c=1..5): g_M[(c-1)][n][j] = sum_f A[n][f] * Wrel[c-1][f][j]
#define BM 128
#define BN 128
#define BK 16

__global__ __launch_bounds__(256, 2)
void gemm_kernel(const float* __restrict__ A, int Din,
                 const float* __restrict__ Broot,
                 const float* __restrict__ Wrel,
                 const float* __restrict__ bias,
                 float* __restrict__ outSelf) {
    const int c = blockIdx.y;  // 0..5
    const float* B = (c == 0) ? Broot : (Wrel + (size_t)(c - 1) * Din * HID);
    const int rowBase = blockIdx.x * BM;

    __shared__ float As[BK][BM];
    __shared__ float Bs[BK][BN];

    const int t  = threadIdx.x;       // 0..255
    const int tx = t & 15;
    const int ty = t >> 4;

    float acc[8][8];
#pragma unroll
    for (int i = 0; i < 8; i++)
#pragma unroll
        for (int j = 0; j < 8; j++) acc[i][j] = 0.0f;

    const int nK = (Din + BK - 1) / BK;
    for (int kt = 0; kt < nK; ++kt) {
        const int k0 = kt * BK;
        // A tile: 2048 elems, 8 scalar loads/thread, stored transposed
#pragma unroll
        for (int i = 0; i < 8; i++) {
            int idx  = t * 8 + i;
            int arow = idx >> 4;
            int ak   = idx & 15;
            int gr   = rowBase + arow;
            int gk   = k0 + ak;
            float v  = 0.0f;
            if (gr < N_NODES && gk < Din) v = A[(size_t)gr * Din + gk];
            As[ak][arow] = v;
        }
        // B tile: 16x128, 2 float4 loads/thread
        {
            int brow = t >> 4;
            int bcol = (t & 15) * 8;
            float4 v0 = make_float4(0, 0, 0, 0), v1 = v0;
            if (k0 + brow < Din) {
                const float4* p = (const float4*)(B + (size_t)(k0 + brow) * HID + bcol);
                v0 = p[0];
                v1 = p[1];
            }
            *(float4*)&Bs[brow][bcol]     = v0;
            *(float4*)&Bs[brow][bcol + 4] = v1;
        }
        __syncthreads();

#pragma unroll
        for (int kk = 0; kk < BK; kk++) {
            float a[8], b[8];
            *(float4*)(a)     = *(const float4*)&As[kk][ty * 8];
            *(float4*)(a + 4) = *(const float4*)&As[kk][ty * 8 + 4];
            *(float4*)(b)     = *(const float4*)&Bs[kk][tx * 8];
            *(float4*)(b + 4) = *(const float4*)&Bs[kk][tx * 8 + 4];
#pragma unroll
            for (int i = 0; i < 8; i++)
#pragma unroll
                for (int j = 0; j < 8; j++) acc[i][j] = fmaf(a[i], b[j], acc[i][j]);
        }
        __syncthreads();
    }

    // epilogue
#pragma unroll
    for (int i = 0; i < 8; i++) {
        int gr = rowBase + ty * 8 + i;
        if (gr >= N_NODES) break;
        int col = tx * 8;
        float4 v0, v1;
        v0.x = acc[i][0]; v0.y = acc[i][1]; v0.z = acc[i][2]; v0.w = acc[i][3];
        v1.x = acc[i][4]; v1.y = acc[i][5]; v1.z = acc[i][6]; v1.w = acc[i][7];
        if (c == 0) {
            const float4 b0 = *(const float4*)&bias[col];
            const float4 b1 = *(const float4*)&bias[col + 4];
            v0.x += b0.x; v0.y += b0.y; v0.z += b0.z; v0.w += b0.w;
            v1.x += b1.x; v1.y += b1.y; v1.z += b1.z; v1.w += b1.w;
            float* dst = outSelf + (size_t)gr * HID + col;
            *(float4*)dst       = v0;
            *(float4*)(dst + 4) = v1;
        } else {
            float* dst = g_M + ((size_t)(c - 1) * N_NODES + gr) * HID + col;
            *(float4*)dst       = v0;
            *(float4*)(dst + 4) = v1;
        }
    }
}

// ---------------- edge scatter: out[dst] += M[r][src] * invc[r][dst] ----------------
__global__ void scatter_kernel(const int* __restrict__ e1, const int* __restrict__ e2,
                               const int* __restrict__ e3, const int* __restrict__ e4,
                               const int* __restrict__ e5,
                               float* __restrict__ out) {
    int r = blockIdx.y;
    const int* eis[R_REL] = {e1, e2, e3, e4, e5};
    const int* ei = eis[r];

    int warp = (blockIdx.x * blockDim.x + threadIdx.x) >> 5;
    int lane = threadIdx.x & 31;
    if (warp >= N_EDGES) return;

    int src = ei[warp];
    int dst = ei[N_EDGES + warp];
    float sc = __ldg(&g_invc[r * N_NODES + dst]);

    const float4 m = *(const float4*)(g_M + ((size_t)r * N_NODES + src) * HID + lane * 4);
    float4 v;
    v.x = m.x * sc; v.y = m.y * sc; v.z = m.z * sc; v.w = m.w * sc;

    float* p = out + (size_t)dst * HID + lane * 4;
    asm volatile("red.global.add.v4.f32 [%0], {%1,%2,%3,%4};"
                 :: "l"(p), "f"(v.x), "f"(v.y), "f"(v.z), "f"(v.w)
                 : "memory");
}

__global__ void relu_kernel(float* __restrict__ x, int n4) {
    int i = blockIdx.x * blockDim.x + threadIdx.x;
    if (i < n4) {
        float4 v = ((float4*)x)[i];
        v.x = fmaxf(v.x, 0.f); v.y = fmaxf(v.y, 0.f);
        v.z = fmaxf(v.z, 0.f); v.w = fmaxf(v.w, 0.f);
        ((float4*)x)[i] = v;
    }
}

// ---------------- graph readout (batch is sorted) ----------------
__device__ __forceinline__ int lower_bound_dev(const int* a, int n, int key) {
    int lo = 0, hi = n;
    while (lo < hi) {
        int mid = (lo + hi) >> 1;
        if (a[mid] < key) lo = mid + 1; else hi = mid;
    }
    return lo;
}

__global__ void readout_kernel(const float* __restrict__ h, const int* __restrict__ batch) {
    int g = blockIdx.x;
    int j = threadIdx.x;  // 128
    int lo = lower_bound_dev(batch, N_NODES, g);
    int hi = lower_bound_dev(batch, N_NODES, g + 1);
    float s = 0.0f;
    for (int n = lo; n < hi; n++) s += h[(size_t)n * HID + j];
    int c = hi - lo;
    g_read[g * HID + j] = s / (float)(c > 0 ? c : 1);
}

// ---------------- fused MLP head ----------------
__global__ void mlp_kernel(const float* __restrict__ Wc1, const float* __restrict__ bc1,
                           const float* __restrict__ Wc2, const float* __restrict__ bc2,
                           const float* __restrict__ Wc3, const float* __restrict__ bc3,
                           float* __restrict__ out) {
    int g = blockIdx.x;
    int j = threadIdx.x;  // 128
    __shared__ float row[HID];
    __shared__ float h1[HID];
    __shared__ float h2[HID];

    row[j] = g_read[g * HID + j];
    __syncthreads();

    float acc = bc1[j];
    for (int f = 0; f < HID; f++) acc = fmaf(row[f], Wc1[f * HID + j], acc);
    h1[j] = fmaxf(acc, 0.f);
    __syncthreads();

    acc = bc2[j];
    for (int f = 0; f < HID; f++) acc = fmaf(h1[f], Wc2[f * HID + j], acc);
    h2[j] = fmaxf(acc, 0.f) * Wc3[j];
    __syncthreads();

    for (int s = 64; s > 0; s >>= 1) {
        if (j < s) h2[j] += h2[j + s];
        __syncthreads();
    }
    if (j == 0) out[g] = h2[0] + bc3[0];
}

// ---------------- launch ----------------
extern "C" void kernel_launch(void* const* d_in, const int* in_sizes, int n_in,
                              void* d_out, int out_size) {
    // Inputs may be ordered either as the reference() signature
    //   (X, ei1..ei5, batch, weights...)
    // or as the setup_inputs() dict insertion order
    //   (X, batch, ei1..ei5, weights...).
    // Disambiguate by element count: edge tensors have 2*E = 240000 elems,
    // batch has N = 100000 elems.
    const float* X = (const float*)d_in[0];
    const int* e[R_REL];
    const int* batch;
    if (in_sizes[1] == 2 * N_EDGES) {
        // signature order: ei at 1..5, batch at 6
        for (int r = 0; r < R_REL; r++) e[r] = (const int*)d_in[1 + r];
        batch = (const int*)d_in[6];
    } else {
        // dict order: batch at 1, ei at 2..6
        batch = (const int*)d_in[1];
        for (int r = 0; r < R_REL; r++) e[r] = (const int*)d_in[2 + r];
    }
    const float* W0    = (const float*)d_in[7];   // R x IN x HID
    const float* root0 = (const float*)d_in[8];   // IN x HID
    const float* b0    = (const float*)d_in[9];   // HID
    const float* Wl    = (const float*)d_in[10];  // L x R x HID x HID
    const float* rootl = (const float*)d_in[11];  // L x HID x HID
    const float* bl    = (const float*)d_in[12];  // L x HID
    const float* Wc1   = (const float*)d_in[13];
    const float* bc1   = (const float*)d_in[14];
    const float* Wc2   = (const float*)d_in[15];
    const float* bc2   = (const float*)d_in[16];
    const float* Wc3   = (const float*)d_in[17];
    const float* bc3   = (const float*)d_in[18];
    float*       out   = (float*)d_out;

    float* bufA; cudaGetSymbolAddress((void**)&bufA, g_bufA);
    float* bufB; cudaGetSymbolAddress((void**)&bufB, g_bufB);

    // --- edge counts -> invc (fixed across layers) ---
    zero_cnt_kernel<<<(R_REL * N_NODES + 255) / 256, 256>>>();
    {
        dim3 grid((N_EDGES + 255) / 256, R_REL);
        count_kernel<<<grid, 256>>>(e[0], e[1], e[2], e[3], e[4]);
    }
    invc_kernel<<<(R_REL * N_NODES + 255) / 256, 256>>>();

    const int gemmRows = (N_NODES + BM - 1) / BM;  // 782
    const int reluN4   = N_NODES * HID / 4;
    dim3 gemmGrid(gemmRows, R_REL + 1);
    dim3 scatGrid((N_EDGES + 7) / 8, R_REL);

    // --- layer 0: X (N x 162) ---
    gemm_kernel<<<gemmGrid, 256>>>(X, IN_DIM, root0, W0, b0, bufA);
    scatter_kernel<<<scatGrid, 256>>>(e[0], e[1], e[2], e[3], e[4], bufA);
    relu_kernel<<<(reluN4 + 255) / 256, 256>>>(bufA, reluN4);

    // --- layer 1 ---
    gemm_kernel<<<gemmGrid, 256>>>(bufA, HID, rootl, Wl, bl, bufB);
    scatter_kernel<<<scatGrid, 256>>>(e[0], e[1], e[2], e[3], e[4], bufB);
    relu_kernel<<<(reluN4 + 255) / 256, 256>>>(bufB, reluN4);

    // --- layer 2 ---
    gemm_kernel<<<gemmGrid, 256>>>(bufB, HID,
                                   rootl + (size_t)HID * HID,
                                   Wl + (size_t)R_REL * HID * HID,
                                   bl + HID, bufA);
    scatter_kernel<<<scatGrid, 256>>>(e[0], e[1], e[2], e[3], e[4], bufA);
    relu_kernel<<<(reluN4 + 255) / 256, 256>>>(bufA, reluN4);

    // --- readout + MLP head ---
    readout_kernel<<<N_GRAPH, HID>>>(bufA, batch);
    mlp_kernel<<<N_GRAPH, HID>>>(Wc1, bc1, Wc2, bc2, Wc3, bc3, out);
}

// round 9
// speedup vs baseline: 1.6924x; 1.6924x over previous
#include <cuda_runtime.h>
#include <cstdint>
#include <cstddef>

#define N_NODES 100000
#define N_EDGES 120000
#define N_GRAPH 256
#define IN_DIM  162
#define HID     128
#define R_REL   5
#define NBLK    6            // root + 5 relations
#define DPAD0   192          // IN_DIM padded to 32
#define DPADH   128
#define PADK    36           // smem row stride (floats): conflict-free frag loads

// ---------------- scratch (static __device__, no allocation) ----------------
__device__ float g_bufA[(size_t)N_NODES * HID];
__device__ float g_bufB[(size_t)N_NODES * HID];
__device__ float g_M[(size_t)R_REL * N_NODES * HID];   // per-relation messages
__device__ float g_Bt[(size_t)NBLK * HID * DPAD0];     // transposed weights, K-major
__device__ int   g_cnt[R_REL * N_NODES];
__device__ float g_invc[R_REL * N_NODES];
__device__ float g_read[N_GRAPH * HID];

// ---------------- small helpers ----------------
__global__ void zero_cnt_kernel() {
    int i = blockIdx.x * blockDim.x + threadIdx.x;
    if (i < R_REL * N_NODES) g_cnt[i] = 0;
}
__global__ void count_kernel(const int* __restrict__ e1, const int* __restrict__ e2,
                             const int* __restrict__ e3, const int* __restrict__ e4,
                             const int* __restrict__ e5) {
    int r = blockIdx.y;
    const int* eis[R_REL] = {e1, e2, e3, e4, e5};
    const int* ei = eis[r];
    int e = blockIdx.x * blockDim.x + threadIdx.x;
    if (e < N_EDGES) atomicAdd(&g_cnt[r * N_NODES + ei[N_EDGES + e]], 1);
}
__global__ void invc_kernel() {
    int i = blockIdx.x * blockDim.x + threadIdx.x;
    if (i < R_REL * N_NODES) {
        int c = g_cnt[i];
        g_invc[i] = 1.0f / (float)(c > 0 ? c : 1);
    }
}

// ---------------- weight transpose: g_Bt[c][j][k] = src_c[k][j], zero-padded k>=Din ----
__global__ void transpose_kernel(const float* __restrict__ root, const float* __restrict__ W,
                                 int Din, int Dpad) {
    __shared__ float tile[32][33];
    int c = blockIdx.z;
    const float* src = (c == 0) ? root : (W + (size_t)(c - 1) * Din * HID);
    int kt = blockIdx.x * 32, jt = blockIdx.y * 32;
    int tx = threadIdx.x, ty = threadIdx.y;  // 32 x 8
#pragma unroll
    for (int i = 0; i < 4; i++) {
        int k = kt + ty + i * 8, j = jt + tx;
        tile[ty + i * 8][tx] = (k < Din) ? src[(size_t)k * HID + j] : 0.0f;
    }
    __syncthreads();
#pragma unroll
    for (int i = 0; i < 4; i++) {
        int j = jt + ty + i * 8, k = kt + tx;
        g_Bt[((size_t)c * HID + j) * Dpad + k] = tile[tx][ty + i * 8];
    }
}

// ---------------- tf32 mma.sync GEMM (baseline sm_80+ feature set) ----------------
__device__ __forceinline__ uint32_t f2tf(float f) {
    uint32_t u;
    asm("cvt.rna.tf32.f32 %0, %1;" : "=r"(u) : "f"(f));
    return u;
}

// smem: As[2][128][PADK], Bs[2][128][PADK] floats
#define GEMM_SMEM (4 * 128 * PADK * 4)

__global__ __launch_bounds__(256, 1)
void gemm_mma_kernel(const float* __restrict__ A, int Din, int Dpad,
                     const float* __restrict__ bias,
                     float* __restrict__ outSelf, int applyRelu) {
    extern __shared__ float sm[];
    float* Asm = sm;                       // [2][128][PADK]
    float* Bsm = sm + 2 * 128 * PADK;      // [2][128][PADK]

    const int c = blockIdx.y;              // 0..5
    const int rowBase = blockIdx.x * 128;
    const int t = threadIdx.x;
    const int wid = t >> 5, lane = t & 31;
    const int warpM = wid >> 2;            // 0..1 (64 rows each)
    const int warpN = wid & 3;             // 0..3 (32 cols each)
    const int lr = lane >> 2;              // 0..7
    const int lc = lane & 3;               // 0..3

    const float* Bt = g_Bt + (size_t)c * HID * Dpad;
    const int nK = Dpad >> 5;

    float cacc[4][4][4];
#pragma unroll
    for (int mt = 0; mt < 4; mt++)
#pragma unroll
        for (int nt = 0; nt < 4; nt++)
#pragma unroll
            for (int q = 0; q < 4; q++) cacc[mt][nt][q] = 0.0f;

    float ar[8][2];     // staging: A 128x32, 8 float2 per thread
    float br[4][4];     // staging: B 128x32, 4 float4 per thread

#define LOADG(I) do {                                                            \
        const int k0_ = (I) * 32;                                                \
        _Pragma("unroll")                                                        \
        for (int p = 0; p < 8; p++) {                                            \
            int lin = p * 256 + t;                                               \
            int row = lin >> 4, c2 = lin & 15;                                   \
            int gr = rowBase + row, gk = k0_ + c2 * 2;                           \
            float2 v = make_float2(0.f, 0.f);                                    \
            if (gr < N_NODES && gk < Din)                                        \
                v = *(const float2*)(A + (size_t)gr * Din + gk);                 \
            if (applyRelu) { v.x = fmaxf(v.x, 0.f); v.y = fmaxf(v.y, 0.f); }     \
            ar[p][0] = v.x; ar[p][1] = v.y;                                      \
        }                                                                        \
        _Pragma("unroll")                                                        \
        for (int p = 0; p < 4; p++) {                                            \
            int lin = p * 256 + t;                                               \
            int j = lin >> 3, c4 = lin & 7;                                      \
            const float4 v = *(const float4*)(Bt + (size_t)j * Dpad + k0_ + c4 * 4); \
            br[p][0] = v.x; br[p][1] = v.y; br[p][2] = v.z; br[p][3] = v.w;      \
        }                                                                        \
    } while (0)

#define STORES(B) do {                                                           \
        float* Ab = Asm + (B) * 128 * PADK;                                      \
        float* Bb = Bsm + (B) * 128 * PADK;                                      \
        _Pragma("unroll")                                                        \
        for (int p = 0; p < 8; p++) {                                            \
            int lin = p * 256 + t;                                               \
            int row = lin >> 4, c2 = lin & 15;                                   \
            uint2 u = make_uint2(f2tf(ar[p][0]), f2tf(ar[p][1]));                \
            *(uint2*)(Ab + row * PADK + c2 * 2) = u;                             \
        }                                                                        \
        _Pragma("unroll")                                                        \
        for (int p = 0; p < 4; p++) {                                            \
            int lin = p * 256 + t;                                               \
            int j = lin >> 3, c4 = lin & 7;                                      \
            uint4 u = make_uint4(f2tf(br[p][0]), f2tf(br[p][1]),                 \
                                 f2tf(br[p][2]), f2tf(br[p][3]));                \
            *(uint4*)(Bb + j * PADK + c4 * 4) = u;                               \
        }                                                                        \
    } while (0)

#define COMPUTE(B) do {                                                          \
        const float* Ab = Asm + (B) * 128 * PADK + (warpM * 64 + lr) * PADK + lc;\
        const float* Bb = Bsm + (B) * 128 * PADK + (warpN * 32 + lr) * PADK + lc;\
        _Pragma("unroll")                                                        \
        for (int ks = 0; ks < 4; ks++) {                                         \
            const int k0_ = ks * 8;                                              \
            uint32_t afr[4][4], bfr[4][2];                                       \
            _Pragma("unroll")                                                    \
            for (int mt = 0; mt < 4; mt++) {                                     \
                const float* pa = Ab + mt * 16 * PADK + k0_;                     \
                afr[mt][0] = *(const uint32_t*)(pa);                             \
                afr[mt][1] = *(const uint32_t*)(pa + 8 * PADK);                  \
                afr[mt][2] = *(const uint32_t*)(pa + 4);                         \
                afr[mt][3] = *(const uint32_t*)(pa + 8 * PADK + 4);              \
            }                                                                    \
            _Pragma("unroll")                                                    \
            for (int nt = 0; nt < 4; nt++) {                                     \
                const float* pb = Bb + nt * 8 * PADK + k0_;                      \
                bfr[nt][0] = *(const uint32_t*)(pb);                             \
                bfr[nt][1] = *(const uint32_t*)(pb + 4);                         \
            }                                                                    \
            _Pragma("unroll")                                                    \
            for (int mt = 0; mt < 4; mt++)                                       \
                _Pragma("unroll")                                                \
                for (int nt = 0; nt < 4; nt++) {                                 \
                    asm volatile(                                                \
                        "mma.sync.aligned.m16n8k8.row.col.f32.tf32.tf32.f32 "    \
                        "{%0,%1,%2,%3}, {%4,%5,%6,%7}, {%8,%9}, {%0,%1,%2,%3};"  \
                        : "+f"(cacc[mt][nt][0]), "+f"(cacc[mt][nt][1]),          \
                          "+f"(cacc[mt][nt][2]), "+f"(cacc[mt][nt][3])           \
                        : "r"(afr[mt][0]), "r"(afr[mt][1]),                      \
                          "r"(afr[mt][2]), "r"(afr[mt][3]),                      \
                          "r"(bfr[nt][0]), "r"(bfr[nt][1]));                     \
                }                                                                \
        }                                                                        \
    } while (0)

    // prologue
    LOADG(0);
    STORES(0);
    __syncthreads();

    for (int i = 0; i < nK; i++) {
        if (i + 1 < nK) LOADG(i + 1);
        COMPUTE(i & 1);
        __syncthreads();
        if (i + 1 < nK) {
            STORES((i + 1) & 1);
            __syncthreads();
        }
    }

    // epilogue: c-frag layout m16n8: c0/c1 at (row=lr, col=2*lc(+1)), c2/c3 at row+8
#pragma unroll
    for (int mt = 0; mt < 4; mt++) {
#pragma unroll
        for (int half = 0; half < 2; half++) {
            int gr = rowBase + warpM * 64 + mt * 16 + lr + half * 8;
            if (gr < N_NODES) {
                float* dst = (c == 0) ? (outSelf + (size_t)gr * HID)
                                      : (g_M + ((size_t)(c - 1) * N_NODES + gr) * HID);
#pragma unroll
                for (int nt = 0; nt < 4; nt++) {
                    int col = warpN * 32 + nt * 8 + lc * 2;
                    float2 v;
                    v.x = cacc[mt][nt][half * 2 + 0];
                    v.y = cacc[mt][nt][half * 2 + 1];
                    if (c == 0) { v.x += bias[col]; v.y += bias[col + 1]; }
                    *(float2*)(dst + col) = v;
                }
            }
        }
    }
#undef LOADG
#undef STORES
#undef COMPUTE
}

// ---------------- edge scatter: out[dst] += M[r][src] * invc[r][dst] ----------------
__global__ void scatter_kernel(const int* __restrict__ e1, const int* __restrict__ e2,
                               const int* __restrict__ e3, const int* __restrict__ e4,
                               const int* __restrict__ e5,
                               float* __restrict__ out) {
    int r = blockIdx.y;
    const int* eis[R_REL] = {e1, e2, e3, e4, e5};
    const int* ei = eis[r];

    int warp = (blockIdx.x * blockDim.x + threadIdx.x) >> 5;
    int lane = threadIdx.x & 31;
    if (warp >= N_EDGES) return;

    int src = ei[warp];
    int dst = ei[N_EDGES + warp];
    float sc = __ldg(&g_invc[r * N_NODES + dst]);

    const float4 m = *(const float4*)(g_M + ((size_t)r * N_NODES + src) * HID + lane * 4);
    float4 v;
    v.x = m.x * sc; v.y = m.y * sc; v.z = m.z * sc; v.w = m.w * sc;

    float* p = out + (size_t)dst * HID + lane * 4;
    asm volatile("red.global.add.v4.f32 [%0], {%1,%2,%3,%4};"
                 :: "l"(p), "f"(v.x), "f"(v.y), "f"(v.z), "f"(v.w)
                 : "memory");
}

// ---------------- graph readout (batch sorted); applies final ReLU ----------------
__device__ __forceinline__ int lower_bound_dev(const int* a, int n, int key) {
    int lo = 0, hi = n;
    while (lo < hi) {
        int mid = (lo + hi) >> 1;
        if (a[mid] < key) lo = mid + 1; else hi = mid;
    }
    return lo;
}
__global__ void readout_kernel(const float* __restrict__ h, const int* __restrict__ batch) {
    int g = blockIdx.x;
    int j = threadIdx.x;  // 128
    int lo = lower_bound_dev(batch, N_NODES, g);
    int hi = lower_bound_dev(batch, N_NODES, g + 1);
    float s = 0.0f;
    for (int n = lo; n < hi; n++) s += fmaxf(h[(size_t)n * HID + j], 0.0f);
    int c = hi - lo;
    g_read[g * HID + j] = s / (float)(c > 0 ? c : 1);
}

// ---------------- fused MLP head ----------------
__global__ void mlp_kernel(const float* __restrict__ Wc1, const float* __restrict__ bc1,
                           const float* __restrict__ Wc2, const float* __restrict__ bc2,
                           const float* __restrict__ Wc3, const float* __restrict__ bc3,
                           float* __restrict__ out) {
    int g = blockIdx.x;
    int j = threadIdx.x;  // 128
    __shared__ float row[HID];
    __shared__ float h1[HID];
    __shared__ float h2[HID];

    row[j] = g_read[g * HID + j];
    __syncthreads();

    float acc = bc1[j];
    for (int f = 0; f < HID; f++) acc = fmaf(row[f], Wc1[f * HID + j], acc);
    h1[j] = fmaxf(acc, 0.f);
    __syncthreads();

    acc = bc2[j];
    for (int f = 0; f < HID; f++) acc = fmaf(h1[f], Wc2[f * HID + j], acc);
    h2[j] = fmaxf(acc, 0.f) * Wc3[j];
    __syncthreads();

    for (int s = 64; s > 0; s >>= 1) {
        if (j < s) h2[j] += h2[j + s];
        __syncthreads();
    }
    if (j == 0) out[g] = h2[0] + bc3[0];
}

// ---------------- launch ----------------
extern "C" void kernel_launch(void* const* d_in, const int* in_sizes, int n_in,
                              void* d_out, int out_size) {
    const float* X = (const float*)d_in[0];
    const int* e[R_REL];
    const int* batch;
    if (in_sizes[1] == 2 * N_EDGES) {
        for (int r = 0; r < R_REL; r++) e[r] = (const int*)d_in[1 + r];
        batch = (const int*)d_in[6];
    } else {
        batch = (const int*)d_in[1];
        for (int r = 0; r < R_REL; r++) e[r] = (const int*)d_in[2 + r];
    }
    const float* W0    = (const float*)d_in[7];
    const float* root0 = (const float*)d_in[8];
    const float* b0    = (const float*)d_in[9];
    const float* Wl    = (const float*)d_in[10];
    const float* rootl = (const float*)d_in[11];
    const float* bl    = (const float*)d_in[12];
    const float* Wc1   = (const float*)d_in[13];
    const float* bc1   = (const float*)d_in[14];
    const float* Wc2   = (const float*)d_in[15];
    const float* bc2   = (const float*)d_in[16];
    const float* Wc3   = (const float*)d_in[17];
    const float* bc3   = (const float*)d_in[18];
    float*       out   = (float*)d_out;

    float* bufA; cudaGetSymbolAddress((void**)&bufA, g_bufA);
    float* bufB; cudaGetSymbolAddress((void**)&bufB, g_bufB);

    cudaFuncSetAttribute(gemm_mma_kernel, cudaFuncAttributeMaxDynamicSharedMemorySize, GEMM_SMEM);

    // edge counts -> invc (fixed across layers)
    zero_cnt_kernel<<<(R_REL * N_NODES + 255) / 256, 256>>>();
    {
        dim3 grid((N_EDGES + 255) / 256, R_REL);
        count_kernel<<<grid, 256>>>(e[0], e[1], e[2], e[3], e[4]);
    }
    invc_kernel<<<(R_REL * N_NODES + 255) / 256, 256>>>();

    const int gemmRows = (N_NODES + 127) / 128;  // 782
    dim3 gemmGrid(gemmRows, NBLK);
    dim3 scatGrid((N_EDGES + 7) / 8, R_REL);
    dim3 tpBlock(32, 8);

    // layer 0: X (N x 162)
    transpose_kernel<<<dim3(DPAD0 / 32, 4, NBLK), tpBlock>>>(root0, W0, IN_DIM, DPAD0);
    gemm_mma_kernel<<<gemmGrid, 256, GEMM_SMEM>>>(X, IN_DIM, DPAD0, b0, bufA, 0);
    scatter_kernel<<<scatGrid, 256>>>(e[0], e[1], e[2], e[3], e[4], bufA);

    // layer 1
    transpose_kernel<<<dim3(DPADH / 32, 4, NBLK), tpBlock>>>(rootl, Wl, HID, DPADH);
    gemm_mma_kernel<<<gemmGrid, 256, GEMM_SMEM>>>(bufA, HID, DPADH, bl, bufB, 1);
    scatter_kernel<<<scatGrid, 256>>>(e[0], e[1], e[2], e[3], e[4], bufB);

    // layer 2
    transpose_kernel<<<dim3(DPADH / 32, 4, NBLK), tpBlock>>>(rootl + (size_t)HID * HID,
                                                             Wl + (size_t)R_REL * HID * HID,
                                                             HID, DPADH);
    gemm_mma_kernel<<<gemmGrid, 256, GEMM_SMEM>>>(bufB, HID, DPADH, bl + HID, bufA, 1);
    scatter_kernel<<<scatGrid, 256>>>(e[0], e[1], e[2], e[3], e[4], bufA);

    // readout (with ReLU) + MLP head
    readout_kernel<<<N_GRAPH, HID>>>(bufA, batch);
    mlp_kernel<<<N_GRAPH, HID>>>(Wc1, bc1, Wc2, bc2, Wc3, bc3, out);
}